// round 1
// baseline (speedup 1.0000x reference)
#include <cuda_runtime.h>

#define NN 10000
#define EE 100000
#define DD 768
#define HH 4
#define CC 192
#define LL 3
#define EDIMF 16
#define NRELC 10

// ---------------- scratch (static device globals; no allocation) ----------------
__device__ float    g_bufA[NN * DD];
__device__ float    g_bufB[NN * DD];
__device__ float    g_q[NN * DD];
__device__ float    g_k[NN * DD];
__device__ float    g_v[NN * DD];
__device__ float    g_skip[NN * DD];
__device__ float    g_ef[EE * EDIMF];
__device__ float    g_P[NN * HH * EDIMF];
__device__ float    g_alpha[EE * HH];
__device__ unsigned g_m[NN * HH];
__device__ float    g_denom[NN * HH];
__device__ float    g_S[NN * HH * EDIMF];

// ---------------- helpers ----------------
__device__ __forceinline__ unsigned encf(float f) {
    unsigned u = __float_as_uint(f);
    return (u & 0x80000000u) ? ~u : (u | 0x80000000u);
}
__device__ __forceinline__ float decf(unsigned u) {
    return (u & 0x80000000u) ? __uint_as_float(u & 0x7FFFFFFFu) : __uint_as_float(~u);
}

// ---------------- edge feature projection: ef = concat(rel_emb[rid], w) @ W_edge + b ----------------
__global__ void ef_kernel(const float* __restrict__ edge_attr, const float* __restrict__ rel_emb,
                          const float* __restrict__ W_edge, const float* __restrict__ b_edge,
                          float* __restrict__ ef) {
    __shared__ float sW[EDIMF * EDIMF];
    __shared__ float sB[EDIMF];
    __shared__ float sR[NRELC * (EDIMF - 1)];
    int t = threadIdx.x;
    if (t < EDIMF * EDIMF) sW[t] = W_edge[t];
    if (t < EDIMF) sB[t] = b_edge[t];
    if (t < NRELC * (EDIMF - 1)) sR[t] = rel_emb[t];
    __syncthreads();
    int e = blockIdx.x * blockDim.x + t;
    if (e >= EE) return;
    int r = (int)edge_attr[2 * e];
    r = min(max(r, 0), NRELC - 1);
    float feat[EDIMF];
#pragma unroll
    for (int i = 0; i < EDIMF - 1; i++) feat[i] = sR[r * (EDIMF - 1) + i];
    feat[EDIMF - 1] = edge_attr[2 * e + 1];
#pragma unroll
    for (int j = 0; j < EDIMF; j++) {
        float s = sB[j];
#pragma unroll
        for (int i = 0; i < EDIMF; i++) s += feat[i] * sW[i * EDIMF + j];
        ef[(size_t)e * EDIMF + j] = s;
    }
}

// ---------------- SGEMM: C[M,Ncols] = A[M,K] @ B[K,Ncols] + bias ----------------
__global__ void __launch_bounds__(256) sgemm_bias_kernel(
    const float* __restrict__ A, const float* __restrict__ B,
    const float* __restrict__ bias, float* __restrict__ C,
    int M, int Ncols, int K) {
    const int BM = 128, BN = 128, BK = 8, TM = 8, TN = 8;
    __shared__ float As[BK][BM];
    __shared__ float Bs[BK][BN];
    int tid = threadIdx.x;
    int bx = blockIdx.x;  // col tile
    int by = blockIdx.y;  // row tile
    int tx = tid & 15;
    int ty = tid >> 4;
    int arow = tid >> 1;
    int acol = (tid & 1) * 4;
    int brow = tid >> 5;
    int bcol = (tid & 31) * 4;
    float acc[TM][TN];
#pragma unroll
    for (int i = 0; i < TM; i++)
#pragma unroll
        for (int j = 0; j < TN; j++) acc[i][j] = 0.f;

    const float* Ab = A + (size_t)by * BM * K;
    const float* Bb = B + bx * BN;
    bool aok = (by * BM + arow) < M;
    for (int k0 = 0; k0 < K; k0 += BK) {
        float4 av = aok ? *(const float4*)(Ab + (size_t)arow * K + k0 + acol)
                        : make_float4(0.f, 0.f, 0.f, 0.f);
        As[acol + 0][arow] = av.x;
        As[acol + 1][arow] = av.y;
        As[acol + 2][arow] = av.z;
        As[acol + 3][arow] = av.w;
        float4 bv = *(const float4*)(Bb + (size_t)(k0 + brow) * Ncols + bcol);
        *(float4*)(&Bs[brow][bcol]) = bv;
        __syncthreads();
#pragma unroll
        for (int kk = 0; kk < BK; kk++) {
            float ra[TM], rb[TN];
#pragma unroll
            for (int i = 0; i < TM; i++) ra[i] = As[kk][ty * TM + i];
#pragma unroll
            for (int j = 0; j < TN; j++) rb[j] = Bs[kk][tx * TN + j];
#pragma unroll
            for (int i = 0; i < TM; i++)
#pragma unroll
                for (int j = 0; j < TN; j++) acc[i][j] = fmaf(ra[i], rb[j], acc[i][j]);
        }
        __syncthreads();
    }
#pragma unroll
    for (int i = 0; i < TM; i++) {
        int gr = by * BM + ty * TM + i;
        if (gr >= M) continue;
        float* Cr = C + (size_t)gr * Ncols + bx * BN + tx * TN;
        const float* br = bias + bx * BN + tx * TN;
#pragma unroll
        for (int j = 0; j < TN; j += 4) {
            float4 o;
            o.x = acc[i][j + 0] + br[j + 0];
            o.y = acc[i][j + 1] + br[j + 1];
            o.z = acc[i][j + 2] + br[j + 2];
            o.w = acc[i][j + 3] + br[j + 3];
            *(float4*)(Cr + j) = o;
        }
    }
}

// ---------------- P[n, h*16+i] = sum_c q[n, h*C+c] * We[i, h*C+c] ----------------
__global__ void p_kernel(const float* __restrict__ q, const float* __restrict__ We,
                         float* __restrict__ P) {
    __shared__ float qs[4][DD];
    int nb = blockIdx.x * 4;
    for (int idx = threadIdx.x; idx < 4 * DD; idx += 256) {
        int nn = nb + idx / DD;
        qs[idx / DD][idx % DD] = (nn < NN) ? q[(size_t)nn * DD + (idx % DD)] : 0.f;
    }
    __syncthreads();
    int local = threadIdx.x / 64;
    int t64 = threadIdx.x % 64;
    int n = nb + local;
    if (n >= NN) return;
    int h = t64 / EDIMF, i = t64 % EDIMF;
    const float* w = We + i * DD + h * CC;
    const float* qq = qs[local] + h * CC;
    float s = 0.f;
#pragma unroll 8
    for (int c = 0; c < CC; c++) s = fmaf(qq[c], w[c], s);
    P[(size_t)n * (HH * EDIMF) + t64] = s;
}

// ---------------- alpha: one warp per edge ----------------
__global__ void alpha_kernel(const float* __restrict__ q, const float* __restrict__ k,
                             const float* __restrict__ P, const float* __restrict__ ef,
                             const int* __restrict__ edge_index,
                             float* __restrict__ alpha, unsigned* __restrict__ m) {
    int warp = (blockIdx.x * blockDim.x + threadIdx.x) >> 5;
    int lane = threadIdx.x & 31;
    if (warp >= EE) return;
    int src = edge_index[warp];
    int dst = edge_index[EE + warp];
    const float* qr = q + (size_t)dst * DD;
    const float* kr = k + (size_t)src * DD;
    const float scale = 0.07216878364870322f;  // 1/sqrt(192)
#pragma unroll
    for (int h = 0; h < HH; h++) {
        float s = 0.f;
#pragma unroll
        for (int j = 0; j < 6; j++) {
            int c = h * CC + lane + 32 * j;
            s = fmaf(qr[c], kr[c], s);
        }
#pragma unroll
        for (int off = 16; off > 0; off >>= 1) s += __shfl_down_sync(0xffffffffu, s, off);
        if (lane == 0) {
            float ed = 0.f;
            const float* pp = P + (size_t)dst * (HH * EDIMF) + h * EDIMF;
            const float* ee = ef + (size_t)warp * EDIMF;
#pragma unroll
            for (int i = 0; i < EDIMF; i++) ed = fmaf(ee[i], pp[i], ed);
            float al = (s + ed) * scale;
            alpha[(size_t)warp * HH + h] = al;
            atomicMax(&m[dst * HH + h], encf(al));
        }
    }
}

// ---------------- exp + denom ----------------
__global__ void expsum_kernel(const int* __restrict__ edge_index, const unsigned* __restrict__ m,
                              float* __restrict__ alpha, float* __restrict__ denom) {
    int idx = blockIdx.x * blockDim.x + threadIdx.x;
    if (idx >= EE * HH) return;
    int e = idx / HH, h = idx % HH;
    int dst = edge_index[EE + e];
    float a = expf(alpha[idx] - decf(m[dst * HH + h]));
    alpha[idx] = a;
    atomicAdd(&denom[dst * HH + h], a);
}

// ---------------- message scatter: out[dst] += a_norm * v[src]; S[dst,h,i] += a_norm*ef[i] ----------------
__global__ void msg_kernel(const float* __restrict__ v, const float* __restrict__ a,
                           const float* __restrict__ denom, const float* __restrict__ ef,
                           const int* __restrict__ edge_index,
                           float* __restrict__ out, float* __restrict__ S) {
    int warp = (blockIdx.x * blockDim.x + threadIdx.x) >> 5;
    int lane = threadIdx.x & 31;
    if (warp >= EE) return;
    int src = edge_index[warp];
    int dst = edge_index[EE + warp];
    float na[HH];
#pragma unroll
    for (int h = 0; h < HH; h++)
        na[h] = a[(size_t)warp * HH + h] / (denom[dst * HH + h] + 1e-16f);
    const float* vr = v + (size_t)src * DD;
    float* outr = out + (size_t)dst * DD;
#pragma unroll
    for (int j = 0; j < 24; j++) {
        int c = lane + 32 * j;
        atomicAdd(&outr[c], na[j / 6] * vr[c]);
    }
    if (lane < EDIMF) {
        float efv = ef[(size_t)warp * EDIMF + lane];
#pragma unroll
        for (int h = 0; h < HH; h++)
            atomicAdd(&S[(size_t)dst * (HH * EDIMF) + h * EDIMF + lane], na[h] * efv);
    }
}

// ---------------- finish: hn += S@We + skip; optional exact GELU ----------------
__global__ void finish_kernel(float* __restrict__ hn, const float* __restrict__ skip,
                              const float* __restrict__ S, const float* __restrict__ We,
                              int gelu) {
    __shared__ float Ss[HH * EDIMF];
    int n = blockIdx.x;
    if (threadIdx.x < HH * EDIMF) Ss[threadIdx.x] = S[(size_t)n * (HH * EDIMF) + threadIdx.x];
    __syncthreads();
    for (int d = threadIdx.x; d < DD; d += blockDim.x) {
        int h = d / CC;
        float s = 0.f;
#pragma unroll
        for (int i = 0; i < EDIMF; i++) s = fmaf(Ss[h * EDIMF + i], We[i * DD + d], s);
        float val = hn[(size_t)n * DD + d] + s + skip[(size_t)n * DD + d];
        if (gelu) val = 0.5f * val * (1.f + erff(val * 0.7071067811865475f));
        hn[(size_t)n * DD + d] = val;
    }
}

// ---------------- layernorm + global mean pool ----------------
__global__ void ln_pool_kernel(const float* __restrict__ h, float* __restrict__ out) {
    __shared__ float red[256];
    int t = threadIdx.x;
    float acc0 = 0.f, acc1 = 0.f, acc2 = 0.f;
    for (int n = blockIdx.x; n < NN; n += gridDim.x) {
        const float* row = h + (size_t)n * DD;
        float v0 = row[t], v1 = row[t + 256], v2 = row[t + 512];
        red[t] = v0 + v1 + v2;
        __syncthreads();
        for (int off = 128; off > 0; off >>= 1) {
            if (t < off) red[t] += red[t + off];
            __syncthreads();
        }
        float mu = red[0] * (1.f / DD);
        __syncthreads();
        float d0 = v0 - mu, d1 = v1 - mu, d2 = v2 - mu;
        red[t] = d0 * d0 + d1 * d1 + d2 * d2;
        __syncthreads();
        for (int off = 128; off > 0; off >>= 1) {
            if (t < off) red[t] += red[t + off];
            __syncthreads();
        }
        float rstd = rsqrtf(red[0] * (1.f / DD) + 1e-5f);
        __syncthreads();
        acc0 += d0 * rstd;
        acc1 += d1 * rstd;
        acc2 += d2 * rstd;
    }
    atomicAdd(&out[t], acc0);
    atomicAdd(&out[t + 256], acc1);
    atomicAdd(&out[t + 512], acc2);
}

__global__ void ln_final_kernel(float* __restrict__ out, const float* __restrict__ g,
                                const float* __restrict__ b) {
    int c = threadIdx.x + blockIdx.x * blockDim.x;
    if (c < DD) out[c] = out[c] * g[c] * (1.f / NN) + b[c];
}

// ---------------- launch ----------------
extern "C" void kernel_launch(void* const* d_in, const int* in_sizes, int n_in,
                              void* d_out, int out_size) {
    const float* x         = (const float*)d_in[0];
    const float* edge_attr = (const float*)d_in[1];
    const int*   edge_index= (const int*)d_in[2];
    const float* rel_emb   = (const float*)d_in[3];
    const float* W_edge    = (const float*)d_in[4];
    const float* b_edge    = (const float*)d_in[5];
    const float* Wk        = (const float*)d_in[6];
    const float* bk        = (const float*)d_in[7];
    const float* Wq        = (const float*)d_in[8];
    const float* bq        = (const float*)d_in[9];
    const float* Wv        = (const float*)d_in[10];
    const float* bv        = (const float*)d_in[11];
    const float* We        = (const float*)d_in[12];
    const float* Wskip     = (const float*)d_in[13];
    const float* bskip     = (const float*)d_in[14];
    const float* ln_g      = (const float*)d_in[15];
    const float* ln_b      = (const float*)d_in[16];
    float* out = (float*)d_out;

    float *bufA, *bufB, *q, *k, *v, *skip, *ef, *P, *alpha, *denom, *S;
    unsigned* m;
    cudaGetSymbolAddress((void**)&bufA, g_bufA);
    cudaGetSymbolAddress((void**)&bufB, g_bufB);
    cudaGetSymbolAddress((void**)&q, g_q);
    cudaGetSymbolAddress((void**)&k, g_k);
    cudaGetSymbolAddress((void**)&v, g_v);
    cudaGetSymbolAddress((void**)&skip, g_skip);
    cudaGetSymbolAddress((void**)&ef, g_ef);
    cudaGetSymbolAddress((void**)&P, g_P);
    cudaGetSymbolAddress((void**)&alpha, g_alpha);
    cudaGetSymbolAddress((void**)&m, g_m);
    cudaGetSymbolAddress((void**)&denom, g_denom);
    cudaGetSymbolAddress((void**)&S, g_S);

    ef_kernel<<<(EE + 255) / 256, 256>>>(edge_attr, rel_emb, W_edge, b_edge, ef);

    const float* hin = x;
    dim3 ggrid(DD / 128, (NN + 127) / 128);
    for (int l = 0; l < LL; l++) {
        const float* Wq_l = Wq + (size_t)l * DD * DD;
        const float* Wk_l = Wk + (size_t)l * DD * DD;
        const float* Wv_l = Wv + (size_t)l * DD * DD;
        const float* Ws_l = Wskip + (size_t)l * DD * DD;
        const float* bq_l = bq + (size_t)l * DD;
        const float* bk_l = bk + (size_t)l * DD;
        const float* bv_l = bv + (size_t)l * DD;
        const float* bs_l = bskip + (size_t)l * DD;
        const float* We_l = We + (size_t)l * EDIMF * DD;

        sgemm_bias_kernel<<<ggrid, 256>>>(hin, Wq_l, bq_l, q, NN, DD, DD);
        sgemm_bias_kernel<<<ggrid, 256>>>(hin, Wk_l, bk_l, k, NN, DD, DD);
        sgemm_bias_kernel<<<ggrid, 256>>>(hin, Wv_l, bv_l, v, NN, DD, DD);
        sgemm_bias_kernel<<<ggrid, 256>>>(hin, Ws_l, bs_l, skip, NN, DD, DD);
        p_kernel<<<(NN + 3) / 4, 256>>>(q, We_l, P);

        float* acc = (l & 1) ? bufB : bufA;
        cudaMemsetAsync(acc, 0, (size_t)NN * DD * sizeof(float));
        cudaMemsetAsync(m, 0, (size_t)NN * HH * sizeof(unsigned));
        cudaMemsetAsync(denom, 0, (size_t)NN * HH * sizeof(float));
        cudaMemsetAsync(S, 0, (size_t)NN * HH * EDIMF * sizeof(float));

        alpha_kernel<<<(EE * 32 + 255) / 256, 256>>>(q, k, P, ef, edge_index, alpha, m);
        expsum_kernel<<<(EE * HH + 255) / 256, 256>>>(edge_index, m, alpha, denom);
        msg_kernel<<<(EE * 32 + 255) / 256, 256>>>(v, alpha, denom, ef, edge_index, acc, S);
        finish_kernel<<<NN, 256>>>(acc, skip, S, We_l, (l < LL - 1) ? 1 : 0);
        hin = acc;
    }

    cudaMemsetAsync(out, 0, DD * sizeof(float));
    ln_pool_kernel<<<1024, 256>>>(hin, out);
    ln_final_kernel<<<3, 256>>>(out, ln_g, ln_b);
}

// round 3
// speedup vs baseline: 1.7342x; 1.7342x over previous
#include <cuda_runtime.h>
#include <cstdint>

#define NN 10000
#define EE 100000
#define DD 768
#define HH 4
#define CC 192
#define LL 3
#define EDIMF 16
#define NRELC 10

// GEMM tiling
#define BM 128
#define BN 128
#define BK 32
#define NKT (DD / BK)     // 24
#define GSTAGES 3
#define SA 36             // A smem row stride (floats): BK + 4
#define SB 132            // B smem row stride (floats): BN + 4
#define AS_FLOATS (BM * SA)          // 4608
#define BS_FLOATS (BK * SB)          // 4224
#define STAGE_FLOATS (AS_FLOATS + BS_FLOATS)
#define GEMM_SMEM (GSTAGES * STAGE_FLOATS * 4)

// ---------------- scratch (static device globals; no allocation) ----------------
__device__ float g_bufA[NN * DD];
__device__ float g_bufB[NN * DD];
__device__ float g_q[NN * DD];
__device__ float g_k[NN * DD];
__device__ float g_v[NN * DD];
__device__ float g_skip[NN * DD];
__device__ float g_ef[EE * EDIMF];
__device__ float g_efcsr[EE * EDIMF];
__device__ float g_alpha[EE * HH];
__device__ int   g_rowptr[NN + 1];
__device__ int   g_cnt[NN];
__device__ int   g_cur[NN];
__device__ int   g_srcidx[EE];
__device__ int   g_eid[EE];

// ---------------- async copy helpers ----------------
__device__ __forceinline__ void cp16(uint32_t dst, const float* src) {
    asm volatile("cp.async.cg.shared.global [%0], [%1], 16;" ::"r"(dst),
                 "l"(__cvta_generic_to_global(src)));
}
__device__ __forceinline__ void cp_commit() { asm volatile("cp.async.commit_group;"); }
__device__ __forceinline__ void cp_wait2() { asm volatile("cp.async.wait_group 2;"); }

// tf32 mma: D(16x8) += A(16x8) * B(8x8), A row-major frag, B col-major frag
__device__ __forceinline__ void mma_tf32(float* c, const uint32_t* a, const uint32_t* b) {
    asm volatile(
        "mma.sync.aligned.m16n8k8.row.col.f32.tf32.tf32.f32 "
        "{%0,%1,%2,%3}, {%4,%5,%6,%7}, {%8,%9}, {%0,%1,%2,%3};"
        : "+f"(c[0]), "+f"(c[1]), "+f"(c[2]), "+f"(c[3])
        : "r"(a[0]), "r"(a[1]), "r"(a[2]), "r"(a[3]), "r"(b[0]), "r"(b[1]));
}

// ================= edge feature projection =================
__global__ void ef_kernel(const float* __restrict__ edge_attr, const float* __restrict__ rel_emb,
                          const float* __restrict__ W_edge, const float* __restrict__ b_edge,
                          float* __restrict__ ef) {
    __shared__ float sW[EDIMF * EDIMF];
    __shared__ float sB[EDIMF];
    __shared__ float sR[NRELC * (EDIMF - 1)];
    int t = threadIdx.x;
    if (t < EDIMF * EDIMF) sW[t] = W_edge[t];
    if (t < EDIMF) sB[t] = b_edge[t];
    if (t < NRELC * (EDIMF - 1)) sR[t] = rel_emb[t];
    __syncthreads();
    int e = blockIdx.x * blockDim.x + t;
    if (e >= EE) return;
    int r = (int)edge_attr[2 * e];
    r = min(max(r, 0), NRELC - 1);
    float feat[EDIMF];
#pragma unroll
    for (int i = 0; i < EDIMF - 1; i++) feat[i] = sR[r * (EDIMF - 1) + i];
    feat[EDIMF - 1] = edge_attr[2 * e + 1];
#pragma unroll
    for (int j = 0; j < EDIMF; j++) {
        float s = sB[j];
#pragma unroll
        for (int i = 0; i < EDIMF; i++) s += feat[i] * sW[i * EDIMF + j];
        ef[(size_t)e * EDIMF + j] = s;
    }
}

// ================= CSR build =================
__global__ void count_kernel(const int* __restrict__ edge_index, int* __restrict__ cnt) {
    int e = blockIdx.x * blockDim.x + threadIdx.x;
    if (e < EE) atomicAdd(&cnt[edge_index[EE + e]], 1);
}

__global__ void scan_kernel(const int* __restrict__ cnt, int* __restrict__ rowptr) {
    __shared__ int s[1024];
    int t = threadIdx.x;
    int carry = 0;
    if (t == 0) rowptr[0] = 0;
    for (int base = 0; base < NN; base += 1024) {
        int i = base + t;
        s[t] = (i < NN) ? cnt[i] : 0;
        __syncthreads();
        for (int off = 1; off < 1024; off <<= 1) {
            int add = (t >= off) ? s[t - off] : 0;
            __syncthreads();
            s[t] += add;
            __syncthreads();
        }
        if (i < NN) rowptr[i + 1] = carry + s[t];
        int tot = s[1023];
        __syncthreads();
        carry += tot;
    }
}

__global__ void scatter_kernel(const int* __restrict__ edge_index, const int* __restrict__ rowptr,
                               int* __restrict__ cur, int* __restrict__ srcs, int* __restrict__ eid) {
    int e = blockIdx.x * blockDim.x + threadIdx.x;
    if (e >= EE) return;
    int dst = edge_index[EE + e];
    int pos = rowptr[dst] + atomicAdd(&cur[dst], 1);
    srcs[pos] = edge_index[e];
    eid[pos] = e;
}

__global__ void ef_reorder_kernel(const float* __restrict__ ef, const int* __restrict__ eid,
                                  float* __restrict__ efc) {
    int idx = blockIdx.x * blockDim.x + threadIdx.x;
    if (idx >= EE * EDIMF) return;
    int pos = idx >> 4, i = idx & 15;
    efc[idx] = ef[(size_t)eid[pos] * EDIMF + i];
}

// ================= fused QKVS GEMM via mma.sync tf32 =================
// C[M=NN, 3072] viewed as 4 weight outputs of 768 cols each.
// grid (24, 79): bx/6 = weight id, bx%6 = 128-col tile; by = 128-row tile.
// 8 warps as 2(m) x 4(n); warp tile 64x32; mma m16n8k8.
__global__ void __launch_bounds__(256) gemm4_kernel(
    const float* __restrict__ A,
    const float* __restrict__ Wq, const float* __restrict__ Wk,
    const float* __restrict__ Wv, const float* __restrict__ Ws,
    const float* __restrict__ b0, const float* __restrict__ b1,
    const float* __restrict__ b2, const float* __restrict__ b3,
    float* __restrict__ o0, float* __restrict__ o1,
    float* __restrict__ o2, float* __restrict__ o3) {
    extern __shared__ float sm[];
    const int t = threadIdx.x;
    const int warp = t >> 5, lane = t & 31;
    const int g = lane >> 2, qd = lane & 3;
    const int w = blockIdx.x / 6;
    const int n0 = (blockIdx.x % 6) * BN;
    const int m0 = blockIdx.y * BM;
    const int wm = warp & 1, wn = warp >> 1;  // 2 x 4 warp grid

    const float* W = (w == 0 ? Wq : w == 1 ? Wk : w == 2 ? Wv : Ws);
    const float* bias = (w == 0 ? b0 : w == 1 ? b1 : w == 2 ? b2 : b3);
    float* out = (w == 0 ? o0 : w == 1 ? o1 : w == 2 ? o2 : o3);

    uint32_t smb = (uint32_t)__cvta_generic_to_shared(sm);

    float c[4][4][4];
#pragma unroll
    for (int mi = 0; mi < 4; mi++)
#pragma unroll
        for (int ni = 0; ni < 4; ni++)
#pragma unroll
            for (int r = 0; r < 4; r++) c[mi][ni][r] = 0.f;

    // stage loader: slot in [0,3), chunk kt (k0 = kt*BK)
    auto load_stage = [&](int slot, int kt) {
        int k0 = kt * BK;
        float* As = sm + slot * STAGE_FLOATS;
        float* Bs = As + AS_FLOATS;
        uint32_t AsB = smb + (uint32_t)(slot * STAGE_FLOATS) * 4u;
        uint32_t BsB = AsB + AS_FLOATS * 4u;
        (void)As; (void)Bs;
        // A: 128 rows x 8 chunks of 16B
#pragma unroll
        for (int s = 0; s < 4; s++) {
            int i = t + s * 256;
            int row = i >> 3, c4 = (i & 7) * 4;
            int grow = m0 + row;
            const float* src = A + (size_t)(grow < NN ? grow : 0) * DD + k0 + c4;
            cp16(AsB + (uint32_t)(row * SA + c4) * 4u, src);
        }
        // B: 32 k-rows x 32 chunks of 16B
#pragma unroll
        for (int s = 0; s < 4; s++) {
            int i = t + s * 256;
            int row = i >> 5, c4 = (i & 31) * 4;
            const float* src = W + (size_t)(k0 + row) * DD + n0 + c4;
            cp16(BsB + (uint32_t)(row * SB + c4) * 4u, src);
        }
    };

#pragma unroll
    for (int s = 0; s < GSTAGES; s++) {
        load_stage(s, s);
        cp_commit();
    }

    for (int kt = 0; kt < NKT; kt++) {
        cp_wait2();
        __syncthreads();
        const float* As = sm + (kt % GSTAGES) * STAGE_FLOATS;
        const float* Bs = As + AS_FLOATS;
#pragma unroll
        for (int ks = 0; ks < 4; ks++) {
            int k0s = ks * 8;
            uint32_t a[4][4], b[4][2];
#pragma unroll
            for (int mi = 0; mi < 4; mi++) {
                int mrow = wm * 64 + mi * 16 + g;
                const float* p = As + mrow * SA + k0s + qd;
                a[mi][0] = __float_as_uint(p[0]);
                a[mi][1] = __float_as_uint(p[8 * SA]);
                a[mi][2] = __float_as_uint(p[4]);
                a[mi][3] = __float_as_uint(p[8 * SA + 4]);
            }
#pragma unroll
            for (int ni = 0; ni < 4; ni++) {
                int ncol = wn * 32 + ni * 8 + g;
                const float* p = Bs + (k0s + qd) * SB + ncol;
                b[ni][0] = __float_as_uint(p[0]);
                b[ni][1] = __float_as_uint(p[4 * SB]);
            }
#pragma unroll
            for (int mi = 0; mi < 4; mi++)
#pragma unroll
                for (int ni = 0; ni < 4; ni++) mma_tf32(c[mi][ni], a[mi], b[ni]);
        }
        __syncthreads();
        if (kt + GSTAGES < NKT) load_stage(kt % GSTAGES, kt + GSTAGES);
        cp_commit();
    }

    // epilogue: write C + bias
#pragma unroll
    for (int mi = 0; mi < 4; mi++) {
#pragma unroll
        for (int rh = 0; rh < 2; rh++) {
            int grow = m0 + wm * 64 + mi * 16 + rh * 8 + g;
            if (grow >= NN) continue;
            float* orow = out + (size_t)grow * DD + n0;
#pragma unroll
            for (int ni = 0; ni < 4; ni++) {
                int col = wn * 32 + ni * 8 + 2 * qd;
                float2 val;
                val.x = c[mi][ni][rh * 2 + 0] + bias[n0 + col];
                val.y = c[mi][ni][rh * 2 + 1] + bias[n0 + col + 1];
                *(float2*)(orow + col) = val;
            }
        }
    }
}

// ================= per-destination-node attention (CSR, no global atomics) =================
__global__ void __launch_bounds__(256) node_attn_kernel(
    const float* __restrict__ q, const float* __restrict__ k, const float* __restrict__ v,
    const float* __restrict__ skip, const float* __restrict__ efc,
    const int* __restrict__ rowptr, const int* __restrict__ srcs,
    const float* __restrict__ We, float* __restrict__ alphas,
    float* __restrict__ out, int gelu) {
    int n = blockIdx.x;
    int t = threadIdx.x, wid = t >> 5, lane = t & 31;
    __shared__ float qs[DD];
    __shared__ float Ps[HH * EDIMF];
    __shared__ float Ss[HH * EDIMF];
    __shared__ float wred[8 * HH];
    __shared__ float mx[HH], dsum[HH], dinv[HH];

    const float* qrow = q + (size_t)n * DD;
    for (int i = t; i < DD; i += 256) qs[i] = qrow[i];
    if (t < HH) dsum[t] = 0.f;
    __syncthreads();
    // P[h,i] = sum_c q[h*C+c] * We[i, h*C+c]
    if (t < 64) {
        int i = t >> 2, h = t & 3;
        const float* wr = We + (size_t)i * DD + h * CC;
        const float* qq = qs + h * CC;
        float s = 0.f;
#pragma unroll 8
        for (int c = 0; c < CC; c++) s = fmaf(qq[c], wr[c], s);
        Ps[h * EDIMF + i] = s;
    }
    __syncthreads();

    int start = rowptr[n], end = rowptr[n + 1];
    const float scale = 0.07216878364870322f;  // 1/sqrt(192)
    float wmax0 = -1e30f, wmax1 = -1e30f, wmax2 = -1e30f, wmax3 = -1e30f;
    // phase A: alphas (warp per edge)
    for (int e = start + wid; e < end; e += 8) {
        int src = srcs[e];
        const float* kr = k + (size_t)src * DD;
        float dots[HH];
#pragma unroll
        for (int h = 0; h < HH; h++) {
            float s = 0.f;
#pragma unroll
            for (int j = 0; j < 6; j++) {
                int c = h * CC + lane + 32 * j;
                s = fmaf(qs[c], kr[c], s);
            }
#pragma unroll
            for (int off = 16; off > 0; off >>= 1) s += __shfl_down_sync(0xffffffffu, s, off);
            dots[h] = s;
        }
        if (lane == 0) {
            const float* ee = efc + (size_t)e * EDIMF;
            float ev[EDIMF];
#pragma unroll
            for (int i = 0; i < EDIMF; i++) ev[i] = ee[i];
#pragma unroll
            for (int h = 0; h < HH; h++) {
                float ed = 0.f;
#pragma unroll
                for (int i = 0; i < EDIMF; i++) ed = fmaf(ev[i], Ps[h * EDIMF + i], ed);
                float al = (dots[h] + ed) * scale;
                alphas[(size_t)e * HH + h] = al;
                if (h == 0) wmax0 = fmaxf(wmax0, al);
                if (h == 1) wmax1 = fmaxf(wmax1, al);
                if (h == 2) wmax2 = fmaxf(wmax2, al);
                if (h == 3) wmax3 = fmaxf(wmax3, al);
            }
        }
    }
    if (lane == 0) {
        wred[wid * HH + 0] = wmax0;
        wred[wid * HH + 1] = wmax1;
        wred[wid * HH + 2] = wmax2;
        wred[wid * HH + 3] = wmax3;
    }
    __syncthreads();
    if (t < HH) {
        float m = wred[t];
#pragma unroll
        for (int ww = 1; ww < 8; ww++) m = fmaxf(m, wred[ww * HH + t]);
        mx[t] = m;
    }
    __syncthreads();
    // phase B: exp + denom
    for (int e = start + t; e < end; e += 256) {
#pragma unroll
        for (int h = 0; h < HH; h++) {
            float a = expf(alphas[(size_t)e * HH + h] - mx[h]);
            alphas[(size_t)e * HH + h] = a;
            atomicAdd(&dsum[h], a);
        }
    }
    __syncthreads();
    if (t < HH) dinv[t] = 1.f / (dsum[t] + 1e-16f);
    __syncthreads();
    // phase C: gather-accumulate messages (thread owns 3 channels)
    int c0 = t, c1 = t + 256, c2 = t + 512;
    int h0 = c0 / CC, h1 = c1 / CC, h2 = c2 / CC;
    float a0 = 0.f, a1 = 0.f, a2 = 0.f;
    float sacc = 0.f;
    int hS = t >> 4, iS = t & 15;
    for (int e = start; e < end; e++) {
        int src = srcs[e];
        const float* vr = v + (size_t)src * DD;
        float w0 = alphas[(size_t)e * HH + h0] * dinv[h0];
        float w1 = alphas[(size_t)e * HH + h1] * dinv[h1];
        float w2 = alphas[(size_t)e * HH + h2] * dinv[h2];
        a0 = fmaf(w0, vr[c0], a0);
        a1 = fmaf(w1, vr[c1], a1);
        a2 = fmaf(w2, vr[c2], a2);
        if (t < 64)
            sacc = fmaf(alphas[(size_t)e * HH + hS] * dinv[hS], efc[(size_t)e * EDIMF + iS], sacc);
    }
    if (t < 64) Ss[hS * EDIMF + iS] = sacc;
    __syncthreads();
    // epilogue: out = msg + S@We + skip (+ gelu)
    const float* sk = skip + (size_t)n * DD;
    float* orow = out + (size_t)n * DD;
#pragma unroll
    for (int m3 = 0; m3 < 3; m3++) {
        int c = t + m3 * 256;
        float a = (m3 == 0) ? a0 : (m3 == 1) ? a1 : a2;
        int h = c / CC;
        float s = 0.f;
#pragma unroll
        for (int i = 0; i < EDIMF; i++) s = fmaf(Ss[h * EDIMF + i], We[(size_t)i * DD + c], s);
        float val = a + s + sk[c];
        if (gelu) val = 0.5f * val * (1.f + erff(val * 0.7071067811865475f));
        orow[c] = val;
    }
}

// ================= layernorm + global mean pool =================
__global__ void ln_pool_kernel(const float* __restrict__ h, float* __restrict__ out) {
    __shared__ float red[256];
    int t = threadIdx.x;
    float acc0 = 0.f, acc1 = 0.f, acc2 = 0.f;
    for (int n = blockIdx.x; n < NN; n += gridDim.x) {
        const float* row = h + (size_t)n * DD;
        float v0 = row[t], v1 = row[t + 256], v2 = row[t + 512];
        red[t] = v0 + v1 + v2;
        __syncthreads();
        for (int off = 128; off > 0; off >>= 1) {
            if (t < off) red[t] += red[t + off];
            __syncthreads();
        }
        float mu = red[0] * (1.f / DD);
        __syncthreads();
        float d0 = v0 - mu, d1 = v1 - mu, d2 = v2 - mu;
        red[t] = d0 * d0 + d1 * d1 + d2 * d2;
        __syncthreads();
        for (int off = 128; off > 0; off >>= 1) {
            if (t < off) red[t] += red[t + off];
            __syncthreads();
        }
        float rstd = rsqrtf(red[0] * (1.f / DD) + 1e-5f);
        __syncthreads();
        acc0 += d0 * rstd;
        acc1 += d1 * rstd;
        acc2 += d2 * rstd;
    }
    atomicAdd(&out[t], acc0);
    atomicAdd(&out[t + 256], acc1);
    atomicAdd(&out[t + 512], acc2);
}

__global__ void ln_final_kernel(float* __restrict__ out, const float* __restrict__ g,
                                const float* __restrict__ b) {
    int c = threadIdx.x + blockIdx.x * blockDim.x;
    if (c < DD) out[c] = out[c] * g[c] * (1.f / NN) + b[c];
}

// ================= launch =================
extern "C" void kernel_launch(void* const* d_in, const int* in_sizes, int n_in,
                              void* d_out, int out_size) {
    const float* x          = (const float*)d_in[0];
    const float* edge_attr  = (const float*)d_in[1];
    const int*   edge_index = (const int*)d_in[2];
    const float* rel_emb    = (const float*)d_in[3];
    const float* W_edge     = (const float*)d_in[4];
    const float* b_edge     = (const float*)d_in[5];
    const float* Wk         = (const float*)d_in[6];
    const float* bk         = (const float*)d_in[7];
    const float* Wq         = (const float*)d_in[8];
    const float* bq         = (const float*)d_in[9];
    const float* Wv         = (const float*)d_in[10];
    const float* bv         = (const float*)d_in[11];
    const float* We         = (const float*)d_in[12];
    const float* Wskip      = (const float*)d_in[13];
    const float* bskip      = (const float*)d_in[14];
    const float* ln_g       = (const float*)d_in[15];
    const float* ln_b       = (const float*)d_in[16];
    float* out = (float*)d_out;

    float *bufA, *bufB, *q, *k, *v, *skip, *ef, *efc, *alpha;
    int *rowptr, *cnt, *cur, *srcidx, *eid;
    cudaGetSymbolAddress((void**)&bufA, g_bufA);
    cudaGetSymbolAddress((void**)&bufB, g_bufB);
    cudaGetSymbolAddress((void**)&q, g_q);
    cudaGetSymbolAddress((void**)&k, g_k);
    cudaGetSymbolAddress((void**)&v, g_v);
    cudaGetSymbolAddress((void**)&skip, g_skip);
    cudaGetSymbolAddress((void**)&ef, g_ef);
    cudaGetSymbolAddress((void**)&efc, g_efcsr);
    cudaGetSymbolAddress((void**)&alpha, g_alpha);
    cudaGetSymbolAddress((void**)&rowptr, g_rowptr);
    cudaGetSymbolAddress((void**)&cnt, g_cnt);
    cudaGetSymbolAddress((void**)&cur, g_cur);
    cudaGetSymbolAddress((void**)&srcidx, g_srcidx);
    cudaGetSymbolAddress((void**)&eid, g_eid);

    cudaFuncSetAttribute(gemm4_kernel, cudaFuncAttributeMaxDynamicSharedMemorySize, GEMM_SMEM);

    // one-time prep
    ef_kernel<<<(EE + 255) / 256, 256>>>(edge_attr, rel_emb, W_edge, b_edge, ef);
    cudaMemsetAsync(cnt, 0, NN * sizeof(int));
    cudaMemsetAsync(cur, 0, NN * sizeof(int));
    count_kernel<<<(EE + 255) / 256, 256>>>(edge_index, cnt);
    scan_kernel<<<1, 1024>>>(cnt, rowptr);
    scatter_kernel<<<(EE + 255) / 256, 256>>>(edge_index, rowptr, cur, srcidx, eid);
    ef_reorder_kernel<<<(EE * EDIMF + 255) / 256, 256>>>(ef, eid, efc);

    const float* hin = x;
    for (int l = 0; l < LL; l++) {
        const float* We_l = We + (size_t)l * EDIMF * DD;
        gemm4_kernel<<<dim3(24, (NN + BM - 1) / BM), 256, GEMM_SMEM>>>(
            hin,
            Wq + (size_t)l * DD * DD, Wk + (size_t)l * DD * DD,
            Wv + (size_t)l * DD * DD, Wskip + (size_t)l * DD * DD,
            bq + (size_t)l * DD, bk + (size_t)l * DD, bv + (size_t)l * DD, bskip + (size_t)l * DD,
            q, k, v, skip);
        float* hout = (l & 1) ? bufB : bufA;
        node_attn_kernel<<<NN, 256>>>(q, k, v, skip, efc, rowptr, srcidx, We_l, alpha, hout,
                                      (l < LL - 1) ? 1 : 0);
        hin = hout;
    }

    cudaMemsetAsync(out, 0, DD * sizeof(float));
    ln_pool_kernel<<<1024, 256>>>(hin, out);
    ln_final_kernel<<<3, 256>>>(out, ln_g, ln_b);
}